// round 15
// baseline (speedup 1.0000x reference)
#include <cuda_runtime.h>
#include <cstdint>

// ---------------------------------------------------------------------------
// SSIM + L1 fused loss, GB300 sm_103a — round 7: latency/overhead attack.
//  * Stage LDGs batched (MLP=18) and prefetched one stage ahead (consumed
//    after pass B => ~full DRAM latency hiding).
//  * Double-buffered v-planes => ONE __syncthreads per stage (was 2).
//  * RB=144 (16 stages): priming overhead 11%->5.6%; grid 1792 = 4.0 waves.
//  * Epilogue re-association: shared fma terms, 24->18 fma slots/pixel.
// Conv math identical to round 6 ((p,q) basis, 4 maps, batched divisions).
// ---------------------------------------------------------------------------

#define IW 1024
#define IH 1024
#define OWID 1016          // valid output dim (VALID 9x9 conv)
#define NIMG 32
#define TW 152             // output cols owned per block
#define THREADS 160        // = loaded cols per block (TW + 8 halo)
#define RB 144             // output rows per block = 16 stages x 9
#define VSTRIDE 161        // floats per v row (161 % 32 == 1 -> conflict-free)
#define VPLANE 1464        // floats per map plane (9*161=1449, +15 pad)
#define BUFF (4 * VPLANE)  // floats per v-buffer (4 maps)

// Gaussian taps, sigma=1.5, normalized (exact separable form of reference w).
constexpr double E0 = 0.02856550;   // exp(-32/9)
constexpr double E1 = 0.13533528;   // exp(-2)
constexpr double E2 = 0.41111229;   // exp(-8/9)
constexpr double E3 = 0.80073740;   // exp(-2/9)
constexpr double GS = 1.0 + 2.0 * (E0 + E1 + E2 + E3);

__device__ constexpr float G[9] = {
    (float)(E0 / GS), (float)(E1 / GS), (float)(E2 / GS), (float)(E3 / GS),
    (float)(1.0 / GS),
    (float)(E3 / GS), (float)(E2 / GS), (float)(E1 / GS), (float)(E0 / GS)
};

__device__ double g_acc[2];  // [0] = sum(1 - S), [1] = sum |x - y|

__global__ void ssim_init_kernel() { g_acc[0] = 0.0; g_acc[1] = 0.0; }

__global__ __launch_bounds__(THREADS, 3) void ssim_main_kernel(
    const float* __restrict__ X, const float* __restrict__ Y) {
    __shared__ float vbuf[2 * BUFF];        // 46.8 KB, double-buffered
    __shared__ float red[2][THREADS / 32];

    const int t   = threadIdx.x;
    const int tx  = blockIdx.x;   // 0..6
    const int ty  = blockIdx.y;   // 0..7
    const int img = blockIdx.z;   // 0..31
    const int ix0 = tx * TW;
    const int iy0 = ty * RB;
    const size_t base = (size_t)img * IW * IH;
    const float* __restrict__ px = X + base + (size_t)iy0 * IW + (ix0 + t);
    const float* __restrict__ py = Y + base + (size_t)iy0 * IW + (ix0 + t);

    const int  gx      = ix0 + t;
    const bool colin   = gx < IW;
    const bool own_col = colin && (t < TW);

    // Vertical ring accumulators: slot = output_row mod 9.  4 maps.
    float ap[9] = {}, aq[9] = {}, app[9] = {}, aqq[9] = {};
    float Ssum = 0.f, l1 = 0.f;
    int   vcnt = 0;

    // ---- priming: rows 0..7 (always in-image: iy0 <= 1008) -----------------
    {
        float rx[8], ry[8];
        #pragma unroll
        for (int p = 0; p < 8; ++p) {       // batched LDGs, MLP=16
            rx[p] = colin ? px[p * IW] : 0.f;
            ry[p] = colin ? py[p * IW] : 0.f;
        }
        #pragma unroll
        for (int p = 0; p < 8; ++p) {
            float pv = rx[p] + ry[p], qv = rx[p] - ry[p];
            if (own_col) l1 += fabsf(qv);
            float ppv = pv * pv, qqv = qv * qv;
            #pragma unroll
            for (int j = 0; j <= p; ++j) {
                const int sl = (p - j) % 9;          // compile-time constant
                ap [sl] += G[j] * pv;
                aq [sl] += G[j] * qv;
                app[sl] += G[j] * ppv;
                aqq[sl] += G[j] * qqv;
            }
        }
    }

    const int vrows = (OWID - iy0 < RB) ? (OWID - iy0) : RB;  // valid out rows
    const int nst   = (vrows + 8) / 9;

    // Pass-B thread mapping: row = t % 9, col-group = t / 9 (9 cols each).
    const int brow = t % 9;
    const int bcg  = t / 9;
    bool lc_ok[9];
    int  n_lc = 0;
    #pragma unroll
    for (int c = 0; c < 9; ++c) {
        lc_ok[c] = (bcg * 9 + c) < TW && (ix0 + bcg * 9 + c) < OWID;
        n_lc += lc_ok[c] ? 1 : 0;
    }

    // Stage-0 input rows (8..16), batched prefetch.
    float sx[9], sy[9];
    {
        const float* pxs = px + 8 * IW;
        const float* pys = py + 8 * IW;
        #pragma unroll
        for (int i = 0; i < 9; ++i) {
            const bool ld = ((iy0 + 8 + i) < IH) && colin;
            sx[i] = ld ? pxs[i * IW] : 0.f;
            sy[i] = ld ? pys[i * IW] : 0.f;
        }
    }

    for (int s = 0; s < nst; ++s) {
        float* wb = vbuf + (s & 1) * BUFF;

        // ---- Pass A: compute from registers, emit v rows 0..8 -------------
        #pragma unroll
        for (int i = 0; i < 9; ++i) {
            float pv = sx[i] + sy[i], qv = sx[i] - sy[i];
            // OOB rows were loaded as 0 => qv = 0 contributes nothing to l1.
            if (own_col && (9 * s + 8 + i) < RB) l1 += fabsf(qv);
            float ppv = pv * pv, qqv = qv * qv;
            #pragma unroll
            for (int j = 0; j < 9; ++j) {
                const int sl = (8 + i - j) % 9;      // compile-time constant
                ap [sl] += G[j] * pv;
                aq [sl] += G[j] * qv;
                app[sl] += G[j] * ppv;
                aqq[sl] += G[j] * qqv;
            }
            wb[0 * VPLANE + i * VSTRIDE + t] = ap [i];
            wb[1 * VPLANE + i * VSTRIDE + t] = aq [i];
            wb[2 * VPLANE + i * VSTRIDE + t] = app[i];
            wb[3 * VPLANE + i * VSTRIDE + t] = aqq[i];
            ap[i] = 0.f; aq[i] = 0.f; app[i] = 0.f; aqq[i] = 0.f;
        }

        // ---- Prefetch next stage (consumed after pass B: latency hidden) --
        if (s + 1 < nst) {
            const float* pxs = px + (9 * (s + 1) + 8) * IW;
            const float* pys = py + (9 * (s + 1) + 8) * IW;
            const int gy0 = iy0 + 9 * (s + 1) + 8;
            #pragma unroll
            for (int i = 0; i < 9; ++i) {
                const bool ld = ((gy0 + i) < IH) && colin;
                sx[i] = ld ? pxs[i * IW] : 0.f;
                sy[i] = ld ? pys[i * IW] : 0.f;
            }
        }
        __syncthreads();   // v-writes visible; all pass-B(s-1) reads done

        // ---- Pass B: horizontal conv, 9 cols per thread, 4 maps -----------
        const float* vrd = wb + brow * VSTRIDE + bcg * 9;
        float oP[9], oQ[9], oPP[9], oQQ[9];
        #define HMAP(M, OUT)                                                  \
        {                                                                     \
            float in[17];                                                     \
            _Pragma("unroll")                                                 \
            for (int k = 0; k < 17; ++k) in[k] = vrd[(M) * VPLANE + k];       \
            _Pragma("unroll")                                                 \
            for (int c = 0; c < 9; ++c) {                                     \
                float a = G[0] * in[c];                                       \
                _Pragma("unroll")                                             \
                for (int k = 1; k < 9; ++k) a += G[k] * in[c + k];            \
                OUT[c] = a;                                                   \
            }                                                                 \
        }
        HMAP(0, oP) HMAP(1, oQ) HMAP(2, oPP) HMAP(3, oQQ)
        #undef HMAP

        const bool rowok = (9 * s + brow) < vrows;
        constexpr float C1  = 0.0004f;    // (0.01*2)^2
        constexpr float K12 = 0.0040f;    // C1 + C2

        float nf[9], df[9];
        #pragma unroll
        for (int c = 0; c < 9; ++c) {
            float P = oP[c], Q = oQ[c], PP = oPP[c], QQ = oQQ[c];
            float a  = P * P;
            float b  = Q * Q;
            float t1 = fmaf( 0.5f, a,  C1);
            float A1 = fmaf(-0.5f, b,  t1);    // .5(a-b)+C1
            float B1 = fmaf( 0.5f, b,  t1);    // .5(a+b)+C1
            float u  = fmaf( 0.5f, PP, K12);
            float u2 = fmaf(-0.5f, QQ, u);
            float A2 = u2 - A1;                // .5((PP-QQ)-(a-b))+C2
            float v2 = fmaf( 0.5f, QQ, u);
            float B2 = v2 - B1;                // .5((PP+QQ)-(a+b))+C2
            bool ok = rowok && lc_ok[c];
            nf[c] = ok ? A1 * A2 : 0.f;
            df[c] = ok ? B1 * B2 : 1.f;
        }
        vcnt += rowok ? n_lc : 0;

        {   // combine {0,1,2,3}: one division for 4 pixels
            float d01 = df[0] * df[1];
            float n01 = nf[0] * df[1] + nf[1] * df[0];
            float d23 = df[2] * df[3];
            float n23 = nf[2] * df[3] + nf[3] * df[2];
            float dG  = d01 * d23;
            float nG  = n01 * d23 + n23 * d01;
            Ssum += __fdividef(nG, dG);
        }
        {   // combine {4,5,6,7,8}: one division for 5 pixels
            float d45 = df[4] * df[5];
            float n45 = nf[4] * df[5] + nf[5] * df[4];
            float d67 = df[6] * df[7];
            float n67 = nf[6] * df[7] + nf[7] * df[6];
            float d47 = d45 * d67;
            float n47 = n45 * d67 + n67 * d45;
            float dG  = d47 * df[8];
            float nG  = n47 * df[8] + nf[8] * d47;
            Ssum += __fdividef(nG, dG);
        }
        // no trailing barrier: next pass A writes the other buffer, and the
        // next stage's barrier proves all reads of this buffer finished
        // before it is written again (two stages later).
    }

    float ssim = (float)vcnt - Ssum;   // sum(1 - S)

    // ---- Block reduction, one double atomic pair per block ----------------
    #pragma unroll
    for (int off = 16; off; off >>= 1) {
        ssim += __shfl_down_sync(0xffffffffu, ssim, off);
        l1   += __shfl_down_sync(0xffffffffu, l1,   off);
    }
    const int w = t >> 5;
    if ((t & 31) == 0) { red[0][w] = ssim; red[1][w] = l1; }
    __syncthreads();
    if (t == 0) {
        float sa = 0.f, la = 0.f;
        #pragma unroll
        for (int i = 0; i < THREADS / 32; ++i) { sa += red[0][i]; la += red[1][i]; }
        atomicAdd(&g_acc[0], (double)sa);
        atomicAdd(&g_acc[1], (double)la);
    }
}

__global__ void ssim_finish_kernel(float* __restrict__ out) {
    double ssim_mean = g_acc[0] / ((double)NIMG * OWID * OWID);
    double l1_mean   = g_acc[1] / ((double)NIMG * IW * IH);
    out[0] = (float)(0.5 * ssim_mean + 1.0 * l1_mean);
}

extern "C" void kernel_launch(void* const* d_in, const int* in_sizes, int n_in,
                              void* d_out, int out_size) {
    const float* X = (const float*)d_in[0];
    const float* Y = (const float*)d_in[1];
    (void)in_sizes; (void)n_in; (void)out_size;

    ssim_init_kernel<<<1, 1>>>();
    dim3 grid((OWID + TW - 1) / TW,   // 7
              (OWID + RB - 1) / RB,   // 8
              NIMG);                  // 32  -> 1792 blocks
    ssim_main_kernel<<<grid, THREADS>>>(X, Y);
    ssim_finish_kernel<<<1, 1>>>((float*)d_out);
}

// round 16
// speedup vs baseline: 1.0054x; 1.0054x over previous
#include <cuda_runtime.h>
#include <cstdint>

// ---------------------------------------------------------------------------
// SSIM + L1 fused loss, GB300 sm_103a — round 7: latency/overhead attack.
//  * Stage LDGs batched (MLP=18) and prefetched one stage ahead (consumed
//    after pass B => ~full DRAM latency hiding).
//  * Double-buffered v-planes => ONE __syncthreads per stage (was 2).
//  * RB=144 (16 stages): priming overhead 11%->5.6%; grid 1792 = 4.0 waves.
//  * Epilogue re-association: shared fma terms, 24->18 fma slots/pixel.
// Conv math identical to round 6 ((p,q) basis, 4 maps, batched divisions).
// ---------------------------------------------------------------------------

#define IW 1024
#define IH 1024
#define OWID 1016          // valid output dim (VALID 9x9 conv)
#define NIMG 32
#define TW 152             // output cols owned per block
#define THREADS 160        // = loaded cols per block (TW + 8 halo)
#define RB 144             // output rows per block = 16 stages x 9
#define VSTRIDE 161        // floats per v row (161 % 32 == 1 -> conflict-free)
#define VPLANE 1464        // floats per map plane (9*161=1449, +15 pad)
#define BUFF (4 * VPLANE)  // floats per v-buffer (4 maps)

// Gaussian taps, sigma=1.5, normalized (exact separable form of reference w).
constexpr double E0 = 0.02856550;   // exp(-32/9)
constexpr double E1 = 0.13533528;   // exp(-2)
constexpr double E2 = 0.41111229;   // exp(-8/9)
constexpr double E3 = 0.80073740;   // exp(-2/9)
constexpr double GS = 1.0 + 2.0 * (E0 + E1 + E2 + E3);

__device__ constexpr float G[9] = {
    (float)(E0 / GS), (float)(E1 / GS), (float)(E2 / GS), (float)(E3 / GS),
    (float)(1.0 / GS),
    (float)(E3 / GS), (float)(E2 / GS), (float)(E1 / GS), (float)(E0 / GS)
};

__device__ double g_acc[2];  // [0] = sum(1 - S), [1] = sum |x - y|

__global__ void ssim_init_kernel() { g_acc[0] = 0.0; g_acc[1] = 0.0; }

__global__ __launch_bounds__(THREADS, 3) void ssim_main_kernel(
    const float* __restrict__ X, const float* __restrict__ Y) {
    __shared__ float vbuf[2 * BUFF];        // 46.8 KB, double-buffered
    __shared__ float red[2][THREADS / 32];

    const int t   = threadIdx.x;
    const int tx  = blockIdx.x;   // 0..6
    const int ty  = blockIdx.y;   // 0..7
    const int img = blockIdx.z;   // 0..31
    const int ix0 = tx * TW;
    const int iy0 = ty * RB;
    const size_t base = (size_t)img * IW * IH;
    const float* __restrict__ px = X + base + (size_t)iy0 * IW + (ix0 + t);
    const float* __restrict__ py = Y + base + (size_t)iy0 * IW + (ix0 + t);

    const int  gx      = ix0 + t;
    const bool colin   = gx < IW;
    const bool own_col = colin && (t < TW);

    // Vertical ring accumulators: slot = output_row mod 9.  4 maps.
    float ap[9] = {}, aq[9] = {}, app[9] = {}, aqq[9] = {};
    float Ssum = 0.f, l1 = 0.f;
    int   vcnt = 0;

    // ---- priming: rows 0..7 (always in-image: iy0 <= 1008) -----------------
    {
        float rx[8], ry[8];
        #pragma unroll
        for (int p = 0; p < 8; ++p) {       // batched LDGs, MLP=16
            rx[p] = colin ? px[p * IW] : 0.f;
            ry[p] = colin ? py[p * IW] : 0.f;
        }
        #pragma unroll
        for (int p = 0; p < 8; ++p) {
            float pv = rx[p] + ry[p], qv = rx[p] - ry[p];
            if (own_col) l1 += fabsf(qv);
            float ppv = pv * pv, qqv = qv * qv;
            #pragma unroll
            for (int j = 0; j <= p; ++j) {
                const int sl = (p - j) % 9;          // compile-time constant
                ap [sl] += G[j] * pv;
                aq [sl] += G[j] * qv;
                app[sl] += G[j] * ppv;
                aqq[sl] += G[j] * qqv;
            }
        }
    }

    const int vrows = (OWID - iy0 < RB) ? (OWID - iy0) : RB;  // valid out rows
    const int nst   = (vrows + 8) / 9;

    // Pass-B thread mapping: row = t % 9, col-group = t / 9 (9 cols each).
    const int brow = t % 9;
    const int bcg  = t / 9;
    bool lc_ok[9];
    int  n_lc = 0;
    #pragma unroll
    for (int c = 0; c < 9; ++c) {
        lc_ok[c] = (bcg * 9 + c) < TW && (ix0 + bcg * 9 + c) < OWID;
        n_lc += lc_ok[c] ? 1 : 0;
    }

    // Stage-0 input rows (8..16), batched prefetch.
    float sx[9], sy[9];
    {
        const float* pxs = px + 8 * IW;
        const float* pys = py + 8 * IW;
        #pragma unroll
        for (int i = 0; i < 9; ++i) {
            const bool ld = ((iy0 + 8 + i) < IH) && colin;
            sx[i] = ld ? pxs[i * IW] : 0.f;
            sy[i] = ld ? pys[i * IW] : 0.f;
        }
    }

    for (int s = 0; s < nst; ++s) {
        float* wb = vbuf + (s & 1) * BUFF;

        // ---- Pass A: compute from registers, emit v rows 0..8 -------------
        #pragma unroll
        for (int i = 0; i < 9; ++i) {
            float pv = sx[i] + sy[i], qv = sx[i] - sy[i];
            // OOB rows were loaded as 0 => qv = 0 contributes nothing to l1.
            if (own_col && (9 * s + 8 + i) < RB) l1 += fabsf(qv);
            float ppv = pv * pv, qqv = qv * qv;
            #pragma unroll
            for (int j = 0; j < 9; ++j) {
                const int sl = (8 + i - j) % 9;      // compile-time constant
                ap [sl] += G[j] * pv;
                aq [sl] += G[j] * qv;
                app[sl] += G[j] * ppv;
                aqq[sl] += G[j] * qqv;
            }
            wb[0 * VPLANE + i * VSTRIDE + t] = ap [i];
            wb[1 * VPLANE + i * VSTRIDE + t] = aq [i];
            wb[2 * VPLANE + i * VSTRIDE + t] = app[i];
            wb[3 * VPLANE + i * VSTRIDE + t] = aqq[i];
            ap[i] = 0.f; aq[i] = 0.f; app[i] = 0.f; aqq[i] = 0.f;
        }

        // ---- Prefetch next stage (consumed after pass B: latency hidden) --
        if (s + 1 < nst) {
            const float* pxs = px + (9 * (s + 1) + 8) * IW;
            const float* pys = py + (9 * (s + 1) + 8) * IW;
            const int gy0 = iy0 + 9 * (s + 1) + 8;
            #pragma unroll
            for (int i = 0; i < 9; ++i) {
                const bool ld = ((gy0 + i) < IH) && colin;
                sx[i] = ld ? pxs[i * IW] : 0.f;
                sy[i] = ld ? pys[i * IW] : 0.f;
            }
        }
        __syncthreads();   // v-writes visible; all pass-B(s-1) reads done

        // ---- Pass B: horizontal conv, 9 cols per thread, 4 maps -----------
        const float* vrd = wb + brow * VSTRIDE + bcg * 9;
        float oP[9], oQ[9], oPP[9], oQQ[9];
        #define HMAP(M, OUT)                                                  \
        {                                                                     \
            float in[17];                                                     \
            _Pragma("unroll")                                                 \
            for (int k = 0; k < 17; ++k) in[k] = vrd[(M) * VPLANE + k];       \
            _Pragma("unroll")                                                 \
            for (int c = 0; c < 9; ++c) {                                     \
                float a = G[0] * in[c];                                       \
                _Pragma("unroll")                                             \
                for (int k = 1; k < 9; ++k) a += G[k] * in[c + k];            \
                OUT[c] = a;                                                   \
            }                                                                 \
        }
        HMAP(0, oP) HMAP(1, oQ) HMAP(2, oPP) HMAP(3, oQQ)
        #undef HMAP

        const bool rowok = (9 * s + brow) < vrows;
        constexpr float C1  = 0.0004f;    // (0.01*2)^2
        constexpr float K12 = 0.0040f;    // C1 + C2

        float nf[9], df[9];
        #pragma unroll
        for (int c = 0; c < 9; ++c) {
            float P = oP[c], Q = oQ[c], PP = oPP[c], QQ = oQQ[c];
            float a  = P * P;
            float b  = Q * Q;
            float t1 = fmaf( 0.5f, a,  C1);
            float A1 = fmaf(-0.5f, b,  t1);    // .5(a-b)+C1
            float B1 = fmaf( 0.5f, b,  t1);    // .5(a+b)+C1
            float u  = fmaf( 0.5f, PP, K12);
            float u2 = fmaf(-0.5f, QQ, u);
            float A2 = u2 - A1;                // .5((PP-QQ)-(a-b))+C2
            float v2 = fmaf( 0.5f, QQ, u);
            float B2 = v2 - B1;                // .5((PP+QQ)-(a+b))+C2
            bool ok = rowok && lc_ok[c];
            nf[c] = ok ? A1 * A2 : 0.f;
            df[c] = ok ? B1 * B2 : 1.f;
        }
        vcnt += rowok ? n_lc : 0;

        {   // combine {0,1,2,3}: one division for 4 pixels
            float d01 = df[0] * df[1];
            float n01 = nf[0] * df[1] + nf[1] * df[0];
            float d23 = df[2] * df[3];
            float n23 = nf[2] * df[3] + nf[3] * df[2];
            float dG  = d01 * d23;
            float nG  = n01 * d23 + n23 * d01;
            Ssum += __fdividef(nG, dG);
        }
        {   // combine {4,5,6,7,8}: one division for 5 pixels
            float d45 = df[4] * df[5];
            float n45 = nf[4] * df[5] + nf[5] * df[4];
            float d67 = df[6] * df[7];
            float n67 = nf[6] * df[7] + nf[7] * df[6];
            float d47 = d45 * d67;
            float n47 = n45 * d67 + n67 * d45;
            float dG  = d47 * df[8];
            float nG  = n47 * df[8] + nf[8] * d47;
            Ssum += __fdividef(nG, dG);
        }
        // no trailing barrier: next pass A writes the other buffer, and the
        // next stage's barrier proves all reads of this buffer finished
        // before it is written again (two stages later).
    }

    float ssim = (float)vcnt - Ssum;   // sum(1 - S)

    // ---- Block reduction, one double atomic pair per block ----------------
    #pragma unroll
    for (int off = 16; off; off >>= 1) {
        ssim += __shfl_down_sync(0xffffffffu, ssim, off);
        l1   += __shfl_down_sync(0xffffffffu, l1,   off);
    }
    const int w = t >> 5;
    if ((t & 31) == 0) { red[0][w] = ssim; red[1][w] = l1; }
    __syncthreads();
    if (t == 0) {
        float sa = 0.f, la = 0.f;
        #pragma unroll
        for (int i = 0; i < THREADS / 32; ++i) { sa += red[0][i]; la += red[1][i]; }
        atomicAdd(&g_acc[0], (double)sa);
        atomicAdd(&g_acc[1], (double)la);
    }
}

__global__ void ssim_finish_kernel(float* __restrict__ out) {
    double ssim_mean = g_acc[0] / ((double)NIMG * OWID * OWID);
    double l1_mean   = g_acc[1] / ((double)NIMG * IW * IH);
    out[0] = (float)(0.5 * ssim_mean + 1.0 * l1_mean);
}

extern "C" void kernel_launch(void* const* d_in, const int* in_sizes, int n_in,
                              void* d_out, int out_size) {
    const float* X = (const float*)d_in[0];
    const float* Y = (const float*)d_in[1];
    (void)in_sizes; (void)n_in; (void)out_size;

    ssim_init_kernel<<<1, 1>>>();
    dim3 grid((OWID + TW - 1) / TW,   // 7
              (OWID + RB - 1) / RB,   // 8
              NIMG);                  // 32  -> 1792 blocks
    ssim_main_kernel<<<grid, THREADS>>>(X, Y);
    ssim_finish_kernel<<<1, 1>>>((float*)d_out);
}

// round 17
// speedup vs baseline: 1.0099x; 1.0045x over previous
#include <cuda_runtime.h>
#include <cstdint>

// ---------------------------------------------------------------------------
// SSIM + L1 fused loss, GB300 sm_103a — round 7: latency/overhead attack.
//  * Stage LDGs batched (MLP=18) and prefetched one stage ahead (consumed
//    after pass B => ~full DRAM latency hiding).
//  * Double-buffered v-planes => ONE __syncthreads per stage (was 2).
//  * RB=144 (16 stages): priming overhead 11%->5.6%; grid 1792 = 4.0 waves.
//  * Epilogue re-association: shared fma terms, 24->18 fma slots/pixel.
// Conv math identical to round 6 ((p,q) basis, 4 maps, batched divisions).
// ---------------------------------------------------------------------------

#define IW 1024
#define IH 1024
#define OWID 1016          // valid output dim (VALID 9x9 conv)
#define NIMG 32
#define TW 152             // output cols owned per block
#define THREADS 160        // = loaded cols per block (TW + 8 halo)
#define RB 144             // output rows per block = 16 stages x 9
#define VSTRIDE 161        // floats per v row (161 % 32 == 1 -> conflict-free)
#define VPLANE 1464        // floats per map plane (9*161=1449, +15 pad)
#define BUFF (4 * VPLANE)  // floats per v-buffer (4 maps)

// Gaussian taps, sigma=1.5, normalized (exact separable form of reference w).
constexpr double E0 = 0.02856550;   // exp(-32/9)
constexpr double E1 = 0.13533528;   // exp(-2)
constexpr double E2 = 0.41111229;   // exp(-8/9)
constexpr double E3 = 0.80073740;   // exp(-2/9)
constexpr double GS = 1.0 + 2.0 * (E0 + E1 + E2 + E3);

__device__ constexpr float G[9] = {
    (float)(E0 / GS), (float)(E1 / GS), (float)(E2 / GS), (float)(E3 / GS),
    (float)(1.0 / GS),
    (float)(E3 / GS), (float)(E2 / GS), (float)(E1 / GS), (float)(E0 / GS)
};

__device__ double g_acc[2];  // [0] = sum(1 - S), [1] = sum |x - y|

__global__ void ssim_init_kernel() { g_acc[0] = 0.0; g_acc[1] = 0.0; }

__global__ __launch_bounds__(THREADS, 3) void ssim_main_kernel(
    const float* __restrict__ X, const float* __restrict__ Y) {
    __shared__ float vbuf[2 * BUFF];        // 46.8 KB, double-buffered
    __shared__ float red[2][THREADS / 32];

    const int t   = threadIdx.x;
    const int tx  = blockIdx.x;   // 0..6
    const int ty  = blockIdx.y;   // 0..7
    const int img = blockIdx.z;   // 0..31
    const int ix0 = tx * TW;
    const int iy0 = ty * RB;
    const size_t base = (size_t)img * IW * IH;
    const float* __restrict__ px = X + base + (size_t)iy0 * IW + (ix0 + t);
    const float* __restrict__ py = Y + base + (size_t)iy0 * IW + (ix0 + t);

    const int  gx      = ix0 + t;
    const bool colin   = gx < IW;
    const bool own_col = colin && (t < TW);

    // Vertical ring accumulators: slot = output_row mod 9.  4 maps.
    float ap[9] = {}, aq[9] = {}, app[9] = {}, aqq[9] = {};
    float Ssum = 0.f, l1 = 0.f;
    int   vcnt = 0;

    // ---- priming: rows 0..7 (always in-image: iy0 <= 1008) -----------------
    {
        float rx[8], ry[8];
        #pragma unroll
        for (int p = 0; p < 8; ++p) {       // batched LDGs, MLP=16
            rx[p] = colin ? px[p * IW] : 0.f;
            ry[p] = colin ? py[p * IW] : 0.f;
        }
        #pragma unroll
        for (int p = 0; p < 8; ++p) {
            float pv = rx[p] + ry[p], qv = rx[p] - ry[p];
            if (own_col) l1 += fabsf(qv);
            float ppv = pv * pv, qqv = qv * qv;
            #pragma unroll
            for (int j = 0; j <= p; ++j) {
                const int sl = (p - j) % 9;          // compile-time constant
                ap [sl] += G[j] * pv;
                aq [sl] += G[j] * qv;
                app[sl] += G[j] * ppv;
                aqq[sl] += G[j] * qqv;
            }
        }
    }

    const int vrows = (OWID - iy0 < RB) ? (OWID - iy0) : RB;  // valid out rows
    const int nst   = (vrows + 8) / 9;

    // Pass-B thread mapping: row = t % 9, col-group = t / 9 (9 cols each).
    const int brow = t % 9;
    const int bcg  = t / 9;
    bool lc_ok[9];
    int  n_lc = 0;
    #pragma unroll
    for (int c = 0; c < 9; ++c) {
        lc_ok[c] = (bcg * 9 + c) < TW && (ix0 + bcg * 9 + c) < OWID;
        n_lc += lc_ok[c] ? 1 : 0;
    }

    // Stage-0 input rows (8..16), batched prefetch.
    float sx[9], sy[9];
    {
        const float* pxs = px + 8 * IW;
        const float* pys = py + 8 * IW;
        #pragma unroll
        for (int i = 0; i < 9; ++i) {
            const bool ld = ((iy0 + 8 + i) < IH) && colin;
            sx[i] = ld ? pxs[i * IW] : 0.f;
            sy[i] = ld ? pys[i * IW] : 0.f;
        }
    }

    for (int s = 0; s < nst; ++s) {
        float* wb = vbuf + (s & 1) * BUFF;

        // ---- Pass A: compute from registers, emit v rows 0..8 -------------
        #pragma unroll
        for (int i = 0; i < 9; ++i) {
            float pv = sx[i] + sy[i], qv = sx[i] - sy[i];
            // OOB rows were loaded as 0 => qv = 0 contributes nothing to l1.
            if (own_col && (9 * s + 8 + i) < RB) l1 += fabsf(qv);
            float ppv = pv * pv, qqv = qv * qv;
            #pragma unroll
            for (int j = 0; j < 9; ++j) {
                const int sl = (8 + i - j) % 9;      // compile-time constant
                ap [sl] += G[j] * pv;
                aq [sl] += G[j] * qv;
                app[sl] += G[j] * ppv;
                aqq[sl] += G[j] * qqv;
            }
            wb[0 * VPLANE + i * VSTRIDE + t] = ap [i];
            wb[1 * VPLANE + i * VSTRIDE + t] = aq [i];
            wb[2 * VPLANE + i * VSTRIDE + t] = app[i];
            wb[3 * VPLANE + i * VSTRIDE + t] = aqq[i];
            ap[i] = 0.f; aq[i] = 0.f; app[i] = 0.f; aqq[i] = 0.f;
        }

        // ---- Prefetch next stage (consumed after pass B: latency hidden) --
        if (s + 1 < nst) {
            const float* pxs = px + (9 * (s + 1) + 8) * IW;
            const float* pys = py + (9 * (s + 1) + 8) * IW;
            const int gy0 = iy0 + 9 * (s + 1) + 8;
            #pragma unroll
            for (int i = 0; i < 9; ++i) {
                const bool ld = ((gy0 + i) < IH) && colin;
                sx[i] = ld ? pxs[i * IW] : 0.f;
                sy[i] = ld ? pys[i * IW] : 0.f;
            }
        }
        __syncthreads();   // v-writes visible; all pass-B(s-1) reads done

        // ---- Pass B: horizontal conv, 9 cols per thread, 4 maps -----------
        const float* vrd = wb + brow * VSTRIDE + bcg * 9;
        float oP[9], oQ[9], oPP[9], oQQ[9];
        #define HMAP(M, OUT)                                                  \
        {                                                                     \
            float in[17];                                                     \
            _Pragma("unroll")                                                 \
            for (int k = 0; k < 17; ++k) in[k] = vrd[(M) * VPLANE + k];       \
            _Pragma("unroll")                                                 \
            for (int c = 0; c < 9; ++c) {                                     \
                float a = G[0] * in[c];                                       \
                _Pragma("unroll")                                             \
                for (int k = 1; k < 9; ++k) a += G[k] * in[c + k];            \
                OUT[c] = a;                                                   \
            }                                                                 \
        }
        HMAP(0, oP) HMAP(1, oQ) HMAP(2, oPP) HMAP(3, oQQ)
        #undef HMAP

        const bool rowok = (9 * s + brow) < vrows;
        constexpr float C1  = 0.0004f;    // (0.01*2)^2
        constexpr float K12 = 0.0040f;    // C1 + C2

        float nf[9], df[9];
        #pragma unroll
        for (int c = 0; c < 9; ++c) {
            float P = oP[c], Q = oQ[c], PP = oPP[c], QQ = oQQ[c];
            float a  = P * P;
            float b  = Q * Q;
            float t1 = fmaf( 0.5f, a,  C1);
            float A1 = fmaf(-0.5f, b,  t1);    // .5(a-b)+C1
            float B1 = fmaf( 0.5f, b,  t1);    // .5(a+b)+C1
            float u  = fmaf( 0.5f, PP, K12);
            float u2 = fmaf(-0.5f, QQ, u);
            float A2 = u2 - A1;                // .5((PP-QQ)-(a-b))+C2
            float v2 = fmaf( 0.5f, QQ, u);
            float B2 = v2 - B1;                // .5((PP+QQ)-(a+b))+C2
            bool ok = rowok && lc_ok[c];
            nf[c] = ok ? A1 * A2 : 0.f;
            df[c] = ok ? B1 * B2 : 1.f;
        }
        vcnt += rowok ? n_lc : 0;

        {   // combine {0,1,2,3}: one division for 4 pixels
            float d01 = df[0] * df[1];
            float n01 = nf[0] * df[1] + nf[1] * df[0];
            float d23 = df[2] * df[3];
            float n23 = nf[2] * df[3] + nf[3] * df[2];
            float dG  = d01 * d23;
            float nG  = n01 * d23 + n23 * d01;
            Ssum += __fdividef(nG, dG);
        }
        {   // combine {4,5,6,7,8}: one division for 5 pixels
            float d45 = df[4] * df[5];
            float n45 = nf[4] * df[5] + nf[5] * df[4];
            float d67 = df[6] * df[7];
            float n67 = nf[6] * df[7] + nf[7] * df[6];
            float d47 = d45 * d67;
            float n47 = n45 * d67 + n67 * d45;
            float dG  = d47 * df[8];
            float nG  = n47 * df[8] + nf[8] * d47;
            Ssum += __fdividef(nG, dG);
        }
        // no trailing barrier: next pass A writes the other buffer, and the
        // next stage's barrier proves all reads of this buffer finished
        // before it is written again (two stages later).
    }

    float ssim = (float)vcnt - Ssum;   // sum(1 - S)

    // ---- Block reduction, one double atomic pair per block ----------------
    #pragma unroll
    for (int off = 16; off; off >>= 1) {
        ssim += __shfl_down_sync(0xffffffffu, ssim, off);
        l1   += __shfl_down_sync(0xffffffffu, l1,   off);
    }
    const int w = t >> 5;
    if ((t & 31) == 0) { red[0][w] = ssim; red[1][w] = l1; }
    __syncthreads();
    if (t == 0) {
        float sa = 0.f, la = 0.f;
        #pragma unroll
        for (int i = 0; i < THREADS / 32; ++i) { sa += red[0][i]; la += red[1][i]; }
        atomicAdd(&g_acc[0], (double)sa);
        atomicAdd(&g_acc[1], (double)la);
    }
}

__global__ void ssim_finish_kernel(float* __restrict__ out) {
    double ssim_mean = g_acc[0] / ((double)NIMG * OWID * OWID);
    double l1_mean   = g_acc[1] / ((double)NIMG * IW * IH);
    out[0] = (float)(0.5 * ssim_mean + 1.0 * l1_mean);
}

extern "C" void kernel_launch(void* const* d_in, const int* in_sizes, int n_in,
                              void* d_out, int out_size) {
    const float* X = (const float*)d_in[0];
    const float* Y = (const float*)d_in[1];
    (void)in_sizes; (void)n_in; (void)out_size;

    ssim_init_kernel<<<1, 1>>>();
    dim3 grid((OWID + TW - 1) / TW,   // 7
              (OWID + RB - 1) / RB,   // 8
              NIMG);                  // 32  -> 1792 blocks
    ssim_main_kernel<<<grid, THREADS>>>(X, Y);
    ssim_finish_kernel<<<1, 1>>>((float*)d_out);
}